// round 4
// baseline (speedup 1.0000x reference)
#include <cuda_runtime.h>

// x (B=8, S=4096, D=1024) fp32. Stats from sequential scan over D of x[0]:
//   m_i = (m_{i-1} + d_i)/i ;  v += (d_i - m_i)^2 ;  var = v/(D-1)
// Segment-parallel scan (state decays by prod 1/i => 16-step warmup is exact
// to ~1e-20). Persistent CTAs: 1024 blocks x 4 rows, double-buffered so the
// scan of row k overlaps the prefetch of row k+1 and streaming keeps DRAM fed.

#define S_DIM 4096
#define D_DIM 1024
#define EPSV  1e-5f
#define WARM  16
#define RPC   4                     // rows per CTA
#define GRID  (S_DIM / RPC)         // 1024

__global__ __launch_bounds__(256)
void ln_fused_kernel(const float* __restrict__ x,
                     const float* __restrict__ alpha,
                     const float* __restrict__ beta,
                     float* __restrict__ out,
                     int B) {
    __shared__ float buf[2][D_DIM + D_DIM / 32];  // swizzle off = idx + (idx>>5)
    __shared__ float rinv[D_DIM];
    __shared__ float s_mean[2], s_rstd[2];

    const int tid  = threadIdx.x;
    const int base = blockIdx.x * RPC;

    // rinv table, once per CTA
    {
        int i = tid * 4;
        rinv[i]     = 1.0f / (float)(i + 1);
        rinv[i + 1] = 1.0f / (float)(i + 2);
        rinv[i + 2] = 1.0f / (float)(i + 3);
        rinv[i + 3] = 1.0f / (float)(i + 4);
    }

    // Prime buf[0] with row `base`
    {
        float4 v = __ldg(((const float4*)(x + (size_t)base * D_DIM)) + tid);
        int bofs = tid * 4;
        int o = bofs + (bofs >> 5);
        buf[0][o]   = v.x; buf[0][o+1] = v.y;
        buf[0][o+2] = v.z; buf[0][o+3] = v.w;
    }
    __syncthreads();

    const float4 a = __ldg(((const float4*)alpha) + tid);
    const float4 b = __ldg(((const float4*)beta)  + tid);

#pragma unroll
    for (int k = 0; k < RPC; ++k) {
        const int cur = k & 1, nxt = cur ^ 1;

        // 1) issue next row's load early (no stall here)
        float4 pre;
        if (k + 1 < RPC)
            pre = __ldg(((const float4*)(x + (size_t)(base + k + 1) * D_DIM)) + tid);

        // 2) warp 0: segment-parallel scan of buf[cur] (overlaps the LDG above)
        if (tid < 32) {
            const int start = tid * 32;
            float m = 0.0f, v = 0.0f;
            if (tid > 0) {
#pragma unroll
                for (int j = WARM; j > 0; --j) {
                    int idx = start - j;
                    float d = buf[cur][idx + (idx >> 5)];
                    float r = rinv[idx];
                    m = fmaf(m, r, d * r);
                }
            }
#pragma unroll
            for (int j = 0; j < 32; ++j) {
                int idx = start + j;
                float d = buf[cur][idx + (idx >> 5)];
                float r = rinv[idx];
                m = fmaf(m, r, d * r);           // (m + d)/i
                float t = d - m;
                v = fmaf(t, t, v);
            }
#pragma unroll
            for (int o = 16; o; o >>= 1)
                v += __shfl_xor_sync(0xffffffffu, v, o);
            float mean = __shfl_sync(0xffffffffu, m, 31);
            if (tid == 0) {
                s_mean[cur] = mean;
                s_rstd[cur] = rsqrtf(v / (float)(D_DIM - 1) + EPSV);
            }
        }

        // 3) stage next row into buf[nxt]
        if (k + 1 < RPC) {
            int bofs = tid * 4;
            int o = bofs + (bofs >> 5);
            buf[nxt][o]   = pre.x; buf[nxt][o+1] = pre.y;
            buf[nxt][o+2] = pre.z; buf[nxt][o+3] = pre.w;
        }
        __syncthreads();

        // 4) stream-normalize all B batches of row base+k (DRAM-bound phase)
        const float m  = s_mean[cur];
        const float rs = s_rstd[cur];
        const size_t rowOff = (size_t)(base + k) * (D_DIM / 4) + tid;

#pragma unroll 8
        for (int bb = 0; bb < B; ++bb) {
            size_t idx = (size_t)bb * S_DIM * (D_DIM / 4) + rowOff;
            float4 xv = __ldcs(((const float4*)x) + idx);
            float4 o;
            o.x = fmaf((xv.x - m) * rs, a.x, b.x);
            o.y = fmaf((xv.y - m) * rs, a.y, b.y);
            o.z = fmaf((xv.z - m) * rs, a.z, b.z);
            o.w = fmaf((xv.w - m) * rs, a.w, b.w);
            __stcs(((float4*)out) + idx, o);
        }
    }
}

extern "C" void kernel_launch(void* const* d_in, const int* in_sizes, int n_in,
                              void* d_out, int out_size) {
    const float* x     = (const float*)d_in[0];
    const float* alpha = (const float*)d_in[1];
    const float* beta  = (const float*)d_in[2];
    float*       out   = (float*)d_out;

    const int B = in_sizes[0] / (S_DIM * D_DIM);

    ln_fused_kernel<<<GRID, 256>>>(x, alpha, beta, out, B);
}

// round 5
// speedup vs baseline: 1.2045x; 1.2045x over previous
#include <cuda_runtime.h>

// x (B=8, S=4096, D=1024) fp32. Stats from sequential scan over D of x[0]:
//   m_i = (m_{i-1} + d_i)/i ;  v += (d_i - m_i)^2 ;  var = v/(D-1)
// Segment-parallel scan: state decays by prod(1/i), so a 16-step warm-up makes
// per-lane segment restarts exact to ~1e-20. One block per row (R3 structure,
// high occupancy). New: the phase-1 row load is kept in registers and reused
// as the b=0 normalize input — saves a 16MB gmem re-read.

#define S_DIM 4096
#define D_DIM 1024
#define EPSV  1e-5f
#define WARM  16

__global__ __launch_bounds__(256)
void ln_fused_kernel(const float* __restrict__ x,
                     const float* __restrict__ alpha,
                     const float* __restrict__ beta,
                     float* __restrict__ out,
                     int B) {
    __shared__ float row[D_DIM + D_DIM / 32];   // swizzle: off = idx + (idx>>5)
    __shared__ float s_stats[2];                // [0]=mean, [1]=rstd

    const int s   = blockIdx.x;
    const int tid = threadIdx.x;

    // ---- Phase 1: coalesced load of x[0,s,:]; keep in regs, stage to smem ----
    const float4 x0v = __ldg(((const float4*)(x + (size_t)s * D_DIM)) + tid);
    {
        int base = tid * 4;                     // base%32 in {0,4,...,28}
        int o = base + (base >> 5);
        row[o]   = x0v.x; row[o+1] = x0v.y;
        row[o+2] = x0v.z; row[o+3] = x0v.w;
    }
    __syncthreads();

    // ---- Phase 2: warp 0 segment-parallel scan (32 lanes x 32 elements) ----
    if (tid < 32) {
        const int start = tid * 32;
        float m = 0.0f, v = 0.0f;

        if (tid > 0) {                          // warm-up rebuilds m to ~1e-20
#pragma unroll
            for (int j = WARM; j > 0; --j) {
                int idx = start - j;
                float d = row[idx + (idx >> 5)];
                float r = __fdividef(1.0f, (float)(idx + 1));
                m = fmaf(m, r, d * r);
            }
        }
#pragma unroll
        for (int j = 0; j < 32; ++j) {
            int idx = start + j;
            float d = row[idx + (idx >> 5)];
            float r = __fdividef(1.0f, (float)(idx + 1));
            m = fmaf(m, r, d * r);              // (m + d)/i
            float t = d - m;
            v = fmaf(t, t, v);
        }
#pragma unroll
        for (int o = 16; o; o >>= 1)
            v += __shfl_xor_sync(0xffffffffu, v, o);
        float mean = __shfl_sync(0xffffffffu, m, 31);
        if (tid == 0) {
            s_stats[0] = mean;
            s_stats[1] = rsqrtf(v / (float)(D_DIM - 1) + EPSV);
        }
    }
    __syncthreads();

    const float m  = s_stats[0];
    const float rs = s_stats[1];

    const float4 a = __ldg(((const float4*)alpha) + tid);
    const float4 b = __ldg(((const float4*)beta)  + tid);

    // ---- Phase 3a: b = 0 straight from registers (no gmem re-read) ----
    {
        size_t idx = (size_t)s * (D_DIM / 4) + tid;
        float4 o;
        o.x = fmaf((x0v.x - m) * rs, a.x, b.x);
        o.y = fmaf((x0v.y - m) * rs, a.y, b.y);
        o.z = fmaf((x0v.z - m) * rs, a.z, b.z);
        o.w = fmaf((x0v.w - m) * rs, a.w, b.w);
        __stcs(((float4*)out) + idx, o);
    }

    // ---- Phase 3b: stream-normalize b = 1..B-1 ----
#pragma unroll 7
    for (int bb = 1; bb < B; ++bb) {
        size_t idx = ((size_t)bb * S_DIM + (size_t)s) * (D_DIM / 4) + tid;
        float4 xv = __ldcs(((const float4*)x) + idx);
        float4 o;
        o.x = fmaf((xv.x - m) * rs, a.x, b.x);
        o.y = fmaf((xv.y - m) * rs, a.y, b.y);
        o.z = fmaf((xv.z - m) * rs, a.z, b.z);
        o.w = fmaf((xv.w - m) * rs, a.w, b.w);
        __stcs(((float4*)out) + idx, o);
    }
}

extern "C" void kernel_launch(void* const* d_in, const int* in_sizes, int n_in,
                              void* d_out, int out_size) {
    const float* x     = (const float*)d_in[0];
    const float* alpha = (const float*)d_in[1];
    const float* beta  = (const float*)d_in[2];
    float*       out   = (float*)d_out;

    const int B = in_sizes[0] / (S_DIM * D_DIM);

    ln_fused_kernel<<<S_DIM, 256>>>(x, alpha, beta, out, B);
}

// round 6
// speedup vs baseline: 1.2628x; 1.0484x over previous
#include <cuda_runtime.h>

// x (B=8, S=4096, D=1024) fp32. Stats from sequential scan over D of x[0]:
//   m_i = (m_{i-1} + d_i)/i ;  v += (d_i - m_i)^2 ;  var = v/(D-1)
// Scan state decays by prod(1/i), so restarting each 4-element segment with a
// <=16-step warm-up is exact to ~1e-20 — the scan parallelizes across all 256
// threads. One block per row; b=0 is normalized from the smem copy (no gmem
// re-read). Regs kept ~32 for full occupancy (R4/R5 lesson).

#define S_DIM 4096
#define D_DIM 1024
#define EPSV  1e-5f
#define WARM  16

__global__ __launch_bounds__(256)
void ln_fused_kernel(const float* __restrict__ x,
                     const float* __restrict__ alpha,
                     const float* __restrict__ beta,
                     float* __restrict__ out,
                     int B) {
    __shared__ float row[D_DIM + D_DIM / 32];   // swizzle: off = idx + (idx>>5)
    __shared__ float s_part[8];                 // per-warp var partials
    __shared__ float s_stats[2];                // [0]=mean, [1]=rstd

    const int s   = blockIdx.x;
    const int tid = threadIdx.x;

    // ---- Phase 1: coalesced load of x[0,s,:] into swizzled smem ----
    {
        float4 v = __ldg(((const float4*)(x + (size_t)s * D_DIM)) + tid);
        int base = tid * 4;
        int o = base + (base >> 5);
        row[o]   = v.x; row[o+1] = v.y;
        row[o+2] = v.z; row[o+3] = v.w;
    }
    __syncthreads();

    // ---- Phase 2: all-thread segment-parallel scan (4 elems/thread) ----
    {
        const int start = tid * 4;
        const int wu    = (start < WARM) ? start : WARM;   // clamp at row start
        float m = 0.0f, v = 0.0f;

        for (int j = wu; j > 0; --j) {           // warm-up (exact for start<16)
            int idx = start - j;
            float d = row[idx + (idx >> 5)];
            float r = __fdividef(1.0f, (float)(idx + 1));
            m = fmaf(m, r, d * r);
        }
#pragma unroll
        for (int j = 0; j < 4; ++j) {
            int idx = start + j;
            float d = row[idx + (idx >> 5)];
            float r = __fdividef(1.0f, (float)(idx + 1));
            m = fmaf(m, r, d * r);               // (m + d)/i
            float t = d - m;
            v = fmaf(t, t, v);                   // var partial (this segment)
        }
        if (tid == 255) s_stats[0] = m;          // m at i = D

#pragma unroll
        for (int o = 16; o; o >>= 1)
            v += __shfl_xor_sync(0xffffffffu, v, o);
        if ((tid & 31) == 0) s_part[tid >> 5] = v;
        __syncthreads();
        if (tid == 0) {
            float vt = s_part[0] + s_part[1] + s_part[2] + s_part[3]
                     + s_part[4] + s_part[5] + s_part[6] + s_part[7];
            s_stats[1] = rsqrtf(vt / (float)(D_DIM - 1) + EPSV);
        }
    }
    __syncthreads();

    const float m  = s_stats[0];
    const float rs = s_stats[1];

    const float4 a = __ldg(((const float4*)alpha) + tid);
    const float4 b = __ldg(((const float4*)beta)  + tid);

    // ---- Phase 3a: b = 0 from the smem copy (saves a 16MB gmem read) ----
    {
        int base = tid * 4;
        int o = base + (base >> 5);
        float4 xv = make_float4(row[o], row[o+1], row[o+2], row[o+3]);
        float4 ov;
        ov.x = fmaf((xv.x - m) * rs, a.x, b.x);
        ov.y = fmaf((xv.y - m) * rs, a.y, b.y);
        ov.z = fmaf((xv.z - m) * rs, a.z, b.z);
        ov.w = fmaf((xv.w - m) * rs, a.w, b.w);
        __stcs(((float4*)out) + (size_t)s * (D_DIM / 4) + tid, ov);
    }

    // ---- Phase 3b: stream-normalize b = 1..B-1 (DRAM-bound) ----
#pragma unroll 7
    for (int bb = 1; bb < B; ++bb) {
        size_t idx = ((size_t)bb * S_DIM + (size_t)s) * (D_DIM / 4) + tid;
        float4 xv = __ldcs(((const float4*)x) + idx);
        float4 ov;
        ov.x = fmaf((xv.x - m) * rs, a.x, b.x);
        ov.y = fmaf((xv.y - m) * rs, a.y, b.y);
        ov.z = fmaf((xv.z - m) * rs, a.z, b.z);
        ov.w = fmaf((xv.w - m) * rs, a.w, b.w);
        __stcs(((float4*)out) + idx, ov);
    }
}

extern "C" void kernel_launch(void* const* d_in, const int* in_sizes, int n_in,
                              void* d_out, int out_size) {
    const float* x     = (const float*)d_in[0];
    const float* alpha = (const float*)d_in[1];
    const float* beta  = (const float*)d_in[2];
    float*       out   = (float*)d_out;

    const int B = in_sizes[0] / (S_DIM * D_DIM);

    ln_fused_kernel<<<S_DIM, 256>>>(x, alpha, beta, out, B);
}

// round 7
// speedup vs baseline: 1.3204x; 1.0457x over previous
#include <cuda_runtime.h>
#include <cuda_pipeline_primitives.h>

// x (B=8, S=4096, D=1024) fp32. Stats from sequential scan over D of x[0]:
//   m_i = (m_{i-1} + d_i)/i ;  v += (d_i - m_i)^2 ;  var = v/(D-1)
// Scan state decays by prod(1/i): 16-step warm-up makes per-segment restarts
// exact to ~1e-20, so the scan parallelizes over all 256 threads.
// One block per row. b=0 normalized from the smem copy (saves 16MB).
// Stream loads double-buffered via cp.async into smem: prefetch for b=1,2 is
// issued BEFORE the scan barriers (hides prologue), each thread consumes only
// its own 16B slice (no barriers in the stream loop), regs stay ~32.

#define S_DIM 4096
#define D_DIM 1024
#define EPSV  1e-5f
#define WARM  16

__global__ __launch_bounds__(256)
void ln_fused_kernel(const float* __restrict__ x,
                     const float* __restrict__ alpha,
                     const float* __restrict__ beta,
                     float* __restrict__ out,
                     int B) {
    __shared__ float row[D_DIM + D_DIM / 32];           // swizzled row of x[0]
    __shared__ __align__(16) float stage[2][D_DIM];     // cp.async ring (8KB)
    __shared__ float s_part[8];
    __shared__ float s_stats[2];

    const int s   = blockIdx.x;
    const int tid = threadIdx.x;
    const size_t rowOff4 = (size_t)s * (D_DIM / 4) + tid;   // float4 index
    const float4* __restrict__ xf = (const float4*)x;

    // ---- Phase 1: coalesced load of x[0,s,:] into swizzled smem ----
    {
        float4 v = __ldg(xf + rowOff4);
        int base = tid * 4;
        int o = base + (base >> 5);
        row[o]   = v.x; row[o+1] = v.y;
        row[o+2] = v.z; row[o+3] = v.w;
    }

    const bool fast = (B == 8);
    if (fast) {
        // prefetch b=1 and b=2 before the scan (latency overlaps scan+barriers)
        __pipeline_memcpy_async(&stage[1][tid * 4],
                                xf + (size_t)1 * S_DIM * (D_DIM / 4) + rowOff4, 16);
        __pipeline_commit();
        __pipeline_memcpy_async(&stage[0][tid * 4],
                                xf + (size_t)2 * S_DIM * (D_DIM / 4) + rowOff4, 16);
        __pipeline_commit();
    }
    __syncthreads();

    // ---- Phase 2: all-thread segment-parallel scan (4 elems/thread) ----
    {
        const int start = tid * 4;
        const int wu    = (start < WARM) ? start : WARM;
        float m = 0.0f, v = 0.0f;

        for (int j = wu; j > 0; --j) {
            int idx = start - j;
            float d = row[idx + (idx >> 5)];
            float r = __fdividef(1.0f, (float)(idx + 1));
            m = fmaf(m, r, d * r);
        }
#pragma unroll
        for (int j = 0; j < 4; ++j) {
            int idx = start + j;
            float d = row[idx + (idx >> 5)];
            float r = __fdividef(1.0f, (float)(idx + 1));
            m = fmaf(m, r, d * r);
            float t = d - m;
            v = fmaf(t, t, v);
        }
        if (tid == 255) s_stats[0] = m;

#pragma unroll
        for (int o = 16; o; o >>= 1)
            v += __shfl_xor_sync(0xffffffffu, v, o);
        if ((tid & 31) == 0) s_part[tid >> 5] = v;
        __syncthreads();
        if (tid == 0) {
            float vt = s_part[0] + s_part[1] + s_part[2] + s_part[3]
                     + s_part[4] + s_part[5] + s_part[6] + s_part[7];
            s_stats[1] = rsqrtf(vt / (float)(D_DIM - 1) + EPSV);
        }
    }
    __syncthreads();

    const float m  = s_stats[0];
    const float rs = s_stats[1];
    const float4 a = __ldg(((const float4*)alpha) + tid);
    const float4 b = __ldg(((const float4*)beta)  + tid);

    // ---- Phase 3a: b = 0 from the smem copy ----
    {
        int base = tid * 4;
        int o = base + (base >> 5);
        float4 ov;
        ov.x = fmaf((row[o]   - m) * rs, a.x, b.x);
        ov.y = fmaf((row[o+1] - m) * rs, a.y, b.y);
        ov.z = fmaf((row[o+2] - m) * rs, a.z, b.z);
        ov.w = fmaf((row[o+3] - m) * rs, a.w, b.w);
        __stcs(((float4*)out) + rowOff4, ov);
    }

    // ---- Phase 3b: stream b = 1..7 through the cp.async ring ----
    if (fast) {
#pragma unroll
        for (int bb = 1; bb < 8; ++bb) {
            if (bb < 7) __pipeline_wait_prior(1);
            else        __pipeline_wait_prior(0);

            float4 xv = *(const float4*)&stage[bb & 1][tid * 4];
            float4 ov;
            ov.x = fmaf((xv.x - m) * rs, a.x, b.x);
            ov.y = fmaf((xv.y - m) * rs, a.y, b.y);
            ov.z = fmaf((xv.z - m) * rs, a.z, b.z);
            ov.w = fmaf((xv.w - m) * rs, a.w, b.w);
            __stcs(((float4*)out) + (size_t)bb * S_DIM * (D_DIM / 4) + rowOff4, ov);

            if (bb + 2 < 8) {   // refill the slot just consumed (own slice only)
                __pipeline_memcpy_async(&stage[bb & 1][tid * 4],
                                        xf + (size_t)(bb + 2) * S_DIM * (D_DIM / 4) + rowOff4, 16);
                __pipeline_commit();
            }
        }
    } else {
        for (int bb = 1; bb < B; ++bb) {
            size_t idx = (size_t)bb * S_DIM * (D_DIM / 4) + rowOff4;
            float4 xv = __ldcs(xf + idx);
            float4 ov;
            ov.x = fmaf((xv.x - m) * rs, a.x, b.x);
            ov.y = fmaf((xv.y - m) * rs, a.y, b.y);
            ov.z = fmaf((xv.z - m) * rs, a.z, b.z);
            ov.w = fmaf((xv.w - m) * rs, a.w, b.w);
            __stcs(((float4*)out) + idx, ov);
        }
    }
}

extern "C" void kernel_launch(void* const* d_in, const int* in_sizes, int n_in,
                              void* d_out, int out_size) {
    const float* x     = (const float*)d_in[0];
    const float* alpha = (const float*)d_in[1];
    const float* beta  = (const float*)d_in[2];
    float*       out   = (float*)d_out;

    const int B = in_sizes[0] / (S_DIM * D_DIM);

    ln_fused_kernel<<<S_DIM, 256>>>(x, alpha, beta, out, B);
}